// round 1
// baseline (speedup 1.0000x reference)
#include <cuda_runtime.h>
#include <cuda_bf16.h>

// Problem constants
#define Bb 4
#define Cc 64
#define Dd 8
#define Nn 4096          // H*W = 64*64
#define LOG2E 1.4426950408889634f

// Scratch (allocation-free rule: __device__ globals)
__device__ float g_q[Bb * Nn * Dd];   // [b][n][d], pre-scaled by log2(e)
__device__ float g_k[Bb * Nn * Dd];   // [b][n][d]
__device__ float g_v[Bb * Nn * Cc];   // [b][n][c]

// ---------- packed f32x2 helpers ----------
__device__ __forceinline__ unsigned long long pack2(float a, float b) {
    unsigned long long r;
    asm("mov.b64 %0, {%1, %2};" : "=l"(r) : "f"(a), "f"(b));
    return r;
}
__device__ __forceinline__ void unpack2(unsigned long long v, float& a, float& b) {
    asm("mov.b64 {%0, %1}, %2;" : "=f"(a), "=f"(b) : "l"(v));
}
__device__ __forceinline__ unsigned long long ffma2(unsigned long long a,
                                                    unsigned long long b,
                                                    unsigned long long c) {
    unsigned long long d;
    asm("fma.rn.f32x2 %0, %1, %2, %3;" : "=l"(d) : "l"(a), "l"(b), "l"(c));
    return d;
}
__device__ __forceinline__ unsigned long long fmul2(unsigned long long a,
                                                    unsigned long long b) {
    unsigned long long d;
    asm("mul.rn.f32x2 %0, %1, %2;" : "=l"(d) : "l"(a), "l"(b));
    return d;
}
__device__ __forceinline__ float ex2f(float x) {
    float y;
    asm("ex2.approx.ftz.f32 %0, %1;" : "=f"(y) : "f"(x));
    return y;
}

// ============================================================
// Kernel 1: fused 1x1-conv QKV projection
//   q[b,n,d] = (Wq[d,:]·x[b,:,n] + bq[d]) * log2e
//   k[b,n,d] =  Wk[d,:]·x[b,:,n] + bk[d]
//   v[b,n,c] =  Wv[c,:]·x[b,:,n] + bv[c]
// grid (N/128, B), 128 threads
// ============================================================
__global__ void __launch_bounds__(128) qkv_kernel(
    const float* __restrict__ x,
    const float* __restrict__ Wq, const float* __restrict__ bq,
    const float* __restrict__ Wk, const float* __restrict__ bk,
    const float* __restrict__ Wv, const float* __restrict__ bv)
{
    __shared__ float sWq[Dd * Cc];
    __shared__ float sWk[Dd * Cc];
    __shared__ float sWv[Cc * Cc];
    __shared__ float sbq[Dd], sbk[Dd], sbv[Cc];

    const int tid = threadIdx.x;
    const int b = blockIdx.y;
    const int n = blockIdx.x * 128 + tid;

    for (int i = tid; i < Dd * Cc; i += 128) { sWq[i] = Wq[i]; sWk[i] = Wk[i]; }
    for (int i = tid; i < Cc * Cc; i += 128) sWv[i] = Wv[i];
    if (tid < Dd) { sbq[tid] = bq[tid]; sbk[tid] = bk[tid]; }
    if (tid < Cc) sbv[tid] = bv[tid];
    __syncthreads();

    float aq[Dd], ak[Dd], av[Cc];
#pragma unroll
    for (int d = 0; d < Dd; d++) { aq[d] = sbq[d]; ak[d] = sbk[d]; }
#pragma unroll
    for (int c = 0; c < Cc; c++) av[c] = sbv[c];

    const float* xp = x + (size_t)b * Cc * Nn + n;
#pragma unroll 4
    for (int c = 0; c < Cc; c++) {
        const float xc = xp[c * Nn];
#pragma unroll
        for (int d = 0; d < Dd; d++) {
            aq[d] = fmaf(sWq[d * Cc + c], xc, aq[d]);
            ak[d] = fmaf(sWk[d * Cc + c], xc, ak[d]);
        }
#pragma unroll
        for (int e = 0; e < Cc; e++)
            av[e] = fmaf(sWv[e * Cc + c], xc, av[e]);
    }

    float4* qd = (float4*)&g_q[((size_t)b * Nn + n) * Dd];
    float4* kd = (float4*)&g_k[((size_t)b * Nn + n) * Dd];
    qd[0] = make_float4(aq[0] * LOG2E, aq[1] * LOG2E, aq[2] * LOG2E, aq[3] * LOG2E);
    qd[1] = make_float4(aq[4] * LOG2E, aq[5] * LOG2E, aq[6] * LOG2E, aq[7] * LOG2E);
    kd[0] = make_float4(ak[0], ak[1], ak[2], ak[3]);
    kd[1] = make_float4(ak[4], ak[5], ak[6], ak[7]);

    float4* vd = (float4*)&g_v[((size_t)b * Nn + n) * Cc];
#pragma unroll
    for (int i = 0; i < Cc / 4; i++)
        vd[i] = make_float4(av[4 * i], av[4 * i + 1], av[4 * i + 2], av[4 * i + 3]);
}

// ============================================================
// Kernel 2: fused flash-style attention + gamma residual
//   BQ=64 queries per CTA, 128 threads: 2 threads per query,
//   each owns 32 output channels. Key tile TK=128 staged in smem.
// grid (N/64, B), 128 threads
// ============================================================
#define TK 128

__global__ void __launch_bounds__(128) attn_kernel(
    const float* __restrict__ x,
    const float* __restrict__ gamma,
    float* __restrict__ out)
{
    __shared__ float  s_k[TK * Dd];        // 4 KB
    __shared__ float4 s_v[TK * (Cc / 4)];  // 32 KB

    const int tid  = threadIdx.x;
    const int b    = blockIdx.y;
    const int half = tid >> 6;             // 0: channels 0..31, 1: 32..63
    const int row  = blockIdx.x * 64 + (tid & 63);

    // load q (pre-scaled by log2e)
    const float4* qp = (const float4*)&g_q[((size_t)b * Nn + row) * Dd];
    const float4 q0 = qp[0];
    const float4 q1 = qp[1];

    float m = -1e30f, l = 0.0f;
    unsigned long long o[16];
#pragma unroll
    for (int i = 0; i < 16; i++) o[i] = 0ull;

    const float4* gk_base = (const float4*)&g_k[(size_t)b * Nn * Dd];
    const float4* gv_base = (const float4*)&g_v[(size_t)b * Nn * Cc];

#pragma unroll 1
    for (int t = 0; t < Nn / TK; t++) {
        // cooperative tile load: K tile 256 float4, V tile 2048 float4
        const float4* gk = gk_base + (size_t)t * TK * (Dd / 4);
        ((float4*)s_k)[tid]       = gk[tid];
        ((float4*)s_k)[tid + 128] = gk[tid + 128];
        const float4* gv = gv_base + (size_t)t * TK * (Cc / 4);
#pragma unroll
        for (int j = 0; j < 16; j++)
            s_v[tid + j * 128] = gv[tid + j * 128];
        __syncthreads();

#pragma unroll 1
        for (int ch = 0; ch < TK / 16; ch++) {
            // --- logits for 16 keys ---
            float s[16];
#pragma unroll
            for (int j = 0; j < 16; j++) {
                const float4* kr = (const float4*)&s_k[(ch * 16 + j) * Dd];
                const float4 a0 = kr[0];
                const float4 a1 = kr[1];
                float acc;
                acc = q0.x * a0.x;
                acc = fmaf(q0.y, a0.y, acc);
                acc = fmaf(q0.z, a0.z, acc);
                acc = fmaf(q0.w, a0.w, acc);
                acc = fmaf(q1.x, a1.x, acc);
                acc = fmaf(q1.y, a1.y, acc);
                acc = fmaf(q1.z, a1.z, acc);
                acc = fmaf(q1.w, a1.w, acc);
                s[j] = acc;
            }
            float cm = s[0];
#pragma unroll
            for (int j = 1; j < 16; j++) cm = fmaxf(cm, s[j]);

            if (cm > m) {
                const float sc = ex2f(m - cm);
                l *= sc;
                const unsigned long long scp = pack2(sc, sc);
#pragma unroll
                for (int i = 0; i < 16; i++) o[i] = fmul2(o[i], scp);
                m = cm;
            }

            // --- accumulate p * v (32 channels per thread, packed f32x2) ---
#pragma unroll
            for (int j = 0; j < 16; j++) {
                const float p = ex2f(s[j] - m);
                l += p;
                const unsigned long long pp = pack2(p, p);
                const ulonglong2* vr =
                    (const ulonglong2*)&s_v[(ch * 16 + j) * (Cc / 4) + half * 8];
#pragma unroll
                for (int i = 0; i < 8; i++) {
                    const ulonglong2 vv = vr[i];
                    o[2 * i]     = ffma2(pp, vv.x, o[2 * i]);
                    o[2 * i + 1] = ffma2(pp, vv.y, o[2 * i + 1]);
                }
            }
        }
        __syncthreads();
    }

    // epilogue: out = gamma * (o / l) + x
    const float inv = 1.0f / l;
    const float gm  = __ldg(gamma);
#pragma unroll
    for (int i = 0; i < 16; i++) {
        float lo, hi;
        unpack2(o[i], lo, hi);
        const int c = half * 32 + 2 * i;
        const size_t idx = ((size_t)b * Cc + c) * Nn + row;
        out[idx]      = fmaf(gm, lo * inv, __ldg(&x[idx]));
        out[idx + Nn] = fmaf(gm, hi * inv, __ldg(&x[idx + Nn]));
    }
}

// ============================================================
extern "C" void kernel_launch(void* const* d_in, const int* in_sizes, int n_in,
                              void* d_out, int out_size)
{
    const float* x     = (const float*)d_in[0];
    const float* Wq    = (const float*)d_in[1];
    const float* bq    = (const float*)d_in[2];
    const float* Wk    = (const float*)d_in[3];
    const float* bk    = (const float*)d_in[4];
    const float* Wv    = (const float*)d_in[5];
    const float* bv    = (const float*)d_in[6];
    const float* gamma = (const float*)d_in[7];
    float* out = (float*)d_out;

    dim3 g1(Nn / 128, Bb);
    qkv_kernel<<<g1, 128>>>(x, Wq, bq, Wk, bk, Wv, bv);

    dim3 g2(Nn / 64, Bb);
    attn_kernel<<<g2, 128>>>(x, gamma, out);
}

// round 2
// speedup vs baseline: 1.4566x; 1.4566x over previous
#include <cuda_runtime.h>
#include <cuda_bf16.h>

// Problem constants
#define Bb 4
#define Cc 64
#define Dd 8
#define Nn 4096          // H*W
#define LOG2E 1.4426950408889634f
#define TK 64            // keys per tile
#define BQ 64            // queries per CTA
#define NT (Nn / TK)     // 64 tiles

// Scratch (allocation-free rule: __device__ globals)
__device__ float g_q[Bb * Nn * Dd];   // [b][n][d], pre-scaled by log2(e)
__device__ float g_k[Bb * Nn * Dd];   // [b][n][d]
__device__ float g_v[Bb * Nn * Cc];   // [b][n][c]

// ---------- packed f32x2 helpers ----------
__device__ __forceinline__ unsigned long long pack2(float a, float b) {
    unsigned long long r;
    asm("mov.b64 %0, {%1, %2};" : "=l"(r) : "f"(a), "f"(b));
    return r;
}
__device__ __forceinline__ void unpack2(unsigned long long v, float& a, float& b) {
    asm("mov.b64 {%0, %1}, %2;" : "=f"(a), "=f"(b) : "l"(v));
}
__device__ __forceinline__ unsigned long long ffma2(unsigned long long a,
                                                    unsigned long long b,
                                                    unsigned long long c) {
    unsigned long long d;
    asm("fma.rn.f32x2 %0, %1, %2, %3;" : "=l"(d) : "l"(a), "l"(b), "l"(c));
    return d;
}
__device__ __forceinline__ float ex2f(float x) {
    float y;
    asm("ex2.approx.ftz.f32 %0, %1;" : "=f"(y) : "f"(x));
    return y;
}

// ============================================================
// Kernel 1: fused 1x1-conv QKV projection (unchanged, ~1% of time)
// ============================================================
__global__ void __launch_bounds__(128) qkv_kernel(
    const float* __restrict__ x,
    const float* __restrict__ Wq, const float* __restrict__ bq,
    const float* __restrict__ Wk, const float* __restrict__ bk,
    const float* __restrict__ Wv, const float* __restrict__ bv)
{
    __shared__ float sWq[Dd * Cc];
    __shared__ float sWk[Dd * Cc];
    __shared__ float sWv[Cc * Cc];
    __shared__ float sbq[Dd], sbk[Dd], sbv[Cc];

    const int tid = threadIdx.x;
    const int b = blockIdx.y;
    const int n = blockIdx.x * 128 + tid;

    for (int i = tid; i < Dd * Cc; i += 128) { sWq[i] = Wq[i]; sWk[i] = Wk[i]; }
    for (int i = tid; i < Cc * Cc; i += 128) sWv[i] = Wv[i];
    if (tid < Dd) { sbq[tid] = bq[tid]; sbk[tid] = bk[tid]; }
    if (tid < Cc) sbv[tid] = bv[tid];
    __syncthreads();

    float aq[Dd], ak[Dd], av[Cc];
#pragma unroll
    for (int d = 0; d < Dd; d++) { aq[d] = sbq[d]; ak[d] = sbk[d]; }
#pragma unroll
    for (int c = 0; c < Cc; c++) av[c] = sbv[c];

    const float* xp = x + (size_t)b * Cc * Nn + n;
#pragma unroll 4
    for (int c = 0; c < Cc; c++) {
        const float xc = xp[c * Nn];
#pragma unroll
        for (int d = 0; d < Dd; d++) {
            aq[d] = fmaf(sWq[d * Cc + c], xc, aq[d]);
            ak[d] = fmaf(sWk[d * Cc + c], xc, ak[d]);
        }
#pragma unroll
        for (int e = 0; e < Cc; e++)
            av[e] = fmaf(sWv[e * Cc + c], xc, av[e]);
    }

    float4* qd = (float4*)&g_q[((size_t)b * Nn + n) * Dd];
    float4* kd = (float4*)&g_k[((size_t)b * Nn + n) * Dd];
    qd[0] = make_float4(aq[0] * LOG2E, aq[1] * LOG2E, aq[2] * LOG2E, aq[3] * LOG2E);
    qd[1] = make_float4(aq[4] * LOG2E, aq[5] * LOG2E, aq[6] * LOG2E, aq[7] * LOG2E);
    kd[0] = make_float4(ak[0], ak[1], ak[2], ak[3]);
    kd[1] = make_float4(ak[4], ak[5], ak[6], ak[7]);

    float4* vd = (float4*)&g_v[((size_t)b * Nn + n) * Cc];
#pragma unroll
    for (int i = 0; i < Cc / 4; i++)
        vd[i] = make_float4(av[4 * i], av[4 * i + 1], av[4 * i + 2], av[4 * i + 3]);
}

// ============================================================
// Kernel 2: attention as a two-phase register-blocked GEMM.
//   CTA: 64 queries, 128 threads. Per tile of TK=64 keys:
//     Phase A: compute P[key][query] = exp2(q·k) into smem (no max — range safe)
//     Phase B: register GEMM, each thread accumulates 4 queries x 8 channels.
//   l (softmax denominator) accumulated in phase A, reduced at the end.
// grid (N/64, B), 128 threads
// ============================================================
__global__ void __launch_bounds__(128) attn_kernel(
    const float* __restrict__ x,
    const float* __restrict__ gamma,
    float* __restrict__ out)
{
    __shared__ float4 s_k4[TK * 2];   // 2 KB  : k[key][0..7]
    __shared__ float4 s_v4[TK * 16];  // 16 KB : v[key][0..63]
    __shared__ float  s_p[TK * BQ];   // 16 KB : p[key][query]

    const int tid  = threadIdx.x;
    const int b    = blockIdx.y;
    const int row0 = blockIdx.x * BQ;
    const int qa   = tid & 15;   // query group: queries qa*4 .. qa*4+3 (both phases)
    const int ka   = tid >> 4;   // phase A: keys ka*8 .. ka*8+7
    const int cb   = tid >> 4;   // phase B: channels cb*8 .. cb*8+7

    // load q for 4 queries (pre-scaled by log2e)
    float q[4][8];
    {
        const float4* qp = (const float4*)&g_q[((size_t)b * Nn + row0 + qa * 4) * Dd];
#pragma unroll
        for (int i = 0; i < 4; i++) {
            float4 a0 = qp[i * 2], a1 = qp[i * 2 + 1];
            q[i][0] = a0.x; q[i][1] = a0.y; q[i][2] = a0.z; q[i][3] = a0.w;
            q[i][4] = a1.x; q[i][5] = a1.y; q[i][6] = a1.z; q[i][7] = a1.w;
        }
    }

    float lpart[4] = {0.f, 0.f, 0.f, 0.f};
    unsigned long long o[4][4];
#pragma unroll
    for (int i = 0; i < 4; i++)
#pragma unroll
        for (int j = 0; j < 4; j++) o[i][j] = 0ull;

    const float4* gk4 = (const float4*)&g_k[(size_t)b * Nn * Dd];  // 2 f4 / key
    const float4* gv4 = (const float4*)&g_v[(size_t)b * Nn * Cc];  // 16 f4 / key

#pragma unroll 1
    for (int t = 0; t < NT; t++) {
        // cooperative tile load: K = 128 float4, V = 1024 float4
        s_k4[tid] = gk4[t * (TK * 2) + tid];
#pragma unroll
        for (int j = 0; j < 8; j++)
            s_v4[tid + j * 128] = gv4[t * (TK * 16) + tid + j * 128];
        __syncthreads();

        // ---- Phase A: logits + exp -> s_p ----
#pragma unroll
        for (int j = 0; j < 8; j++) {
            const int kk = ka * 8 + j;
            const float4 k0 = s_k4[kk * 2];
            const float4 k1 = s_k4[kk * 2 + 1];
            float4 pv;
            float* pp = &pv.x;
#pragma unroll
            for (int i = 0; i < 4; i++) {
                float s = q[i][0] * k0.x;
                s = fmaf(q[i][1], k0.y, s);
                s = fmaf(q[i][2], k0.z, s);
                s = fmaf(q[i][3], k0.w, s);
                s = fmaf(q[i][4], k1.x, s);
                s = fmaf(q[i][5], k1.y, s);
                s = fmaf(q[i][6], k1.z, s);
                s = fmaf(q[i][7], k1.w, s);
                const float p = ex2f(s);
                lpart[i] += p;
                pp[i] = p;
            }
            *(float4*)&s_p[kk * BQ + qa * 4] = pv;
        }
        __syncthreads();

        // ---- Phase B: o += P * V  (4 queries x 8 channels per thread) ----
#pragma unroll 4
        for (int kk = 0; kk < TK; kk++) {
            const float4 pv = *(const float4*)&s_p[kk * BQ + qa * 4];
            const unsigned long long p0 = pack2(pv.x, pv.x);
            const unsigned long long p1 = pack2(pv.y, pv.y);
            const unsigned long long p2 = pack2(pv.z, pv.z);
            const unsigned long long p3 = pack2(pv.w, pv.w);
            const ulonglong2* vr = (const ulonglong2*)&s_v4[kk * 16 + cb * 2];
            const ulonglong2 va = vr[0];
            const ulonglong2 vb = vr[1];
            o[0][0] = ffma2(p0, va.x, o[0][0]);
            o[0][1] = ffma2(p0, va.y, o[0][1]);
            o[0][2] = ffma2(p0, vb.x, o[0][2]);
            o[0][3] = ffma2(p0, vb.y, o[0][3]);
            o[1][0] = ffma2(p1, va.x, o[1][0]);
            o[1][1] = ffma2(p1, va.y, o[1][1]);
            o[1][2] = ffma2(p1, vb.x, o[1][2]);
            o[1][3] = ffma2(p1, vb.y, o[1][3]);
            o[2][0] = ffma2(p2, va.x, o[2][0]);
            o[2][1] = ffma2(p2, va.y, o[2][1]);
            o[2][2] = ffma2(p2, vb.x, o[2][2]);
            o[2][3] = ffma2(p2, vb.y, o[2][3]);
            o[3][0] = ffma2(p3, va.x, o[3][0]);
            o[3][1] = ffma2(p3, va.y, o[3][1]);
            o[3][2] = ffma2(p3, vb.x, o[3][2]);
            o[3][3] = ffma2(p3, vb.y, o[3][3]);
        }
        __syncthreads();
    }

    // ---- l reduction across the 8 ka-groups (reuse s_p) ----
    *(float4*)&s_p[ka * BQ + qa * 4] =
        make_float4(lpart[0], lpart[1], lpart[2], lpart[3]);
    __syncthreads();
    float4 lacc = *(const float4*)&s_p[qa * 4];
#pragma unroll
    for (int g = 1; g < 8; g++) {
        const float4 tl = *(const float4*)&s_p[g * BQ + qa * 4];
        lacc.x += tl.x; lacc.y += tl.y; lacc.z += tl.z; lacc.w += tl.w;
    }
    float linv[4];
    linv[0] = 1.0f / lacc.x;
    linv[1] = 1.0f / lacc.y;
    linv[2] = 1.0f / lacc.z;
    linv[3] = 1.0f / lacc.w;

    // ---- epilogue: out = gamma * (o/l) + x ----
    const float gm = __ldg(gamma);
#pragma unroll
    for (int i = 0; i < 4; i++) {
        const int row = row0 + qa * 4 + i;
#pragma unroll
        for (int cp = 0; cp < 4; cp++) {
            float lo, hi;
            unpack2(o[i][cp], lo, hi);
            const int c = cb * 8 + cp * 2;
            const size_t idx = ((size_t)(b * Cc + c)) * Nn + row;
            out[idx]      = fmaf(gm, lo * linv[i], __ldg(&x[idx]));
            out[idx + Nn] = fmaf(gm, hi * linv[i], __ldg(&x[idx + Nn]));
        }
    }
}

// ============================================================
extern "C" void kernel_launch(void* const* d_in, const int* in_sizes, int n_in,
                              void* d_out, int out_size)
{
    const float* x     = (const float*)d_in[0];
    const float* Wq    = (const float*)d_in[1];
    const float* bq    = (const float*)d_in[2];
    const float* Wk    = (const float*)d_in[3];
    const float* bk    = (const float*)d_in[4];
    const float* Wv    = (const float*)d_in[5];
    const float* bv    = (const float*)d_in[6];
    const float* gamma = (const float*)d_in[7];
    float* out = (float*)d_out;

    dim3 g1(Nn / 128, Bb);
    qkv_kernel<<<g1, 128>>>(x, Wq, bq, Wk, bk, Wv, bv);

    dim3 g2(Nn / BQ, Bb);
    attn_kernel<<<g2, 128>>>(x, gamma, out);
}

// round 4
// speedup vs baseline: 3.7044x; 2.5432x over previous
#include <cuda_runtime.h>
#include <cuda_fp16.h>
#include <cstdint>

// Problem constants
#define Bb 4
#define Cc 64
#define Dd 8
#define Nn 4096          // H*W
#define LOG2E 1.4426950408889634f
#define TK 128           // keys per tile
#define NQ 128           // queries per CTA
#define NT (Nn / TK)     // 32 tiles

// Scratch (allocation-free rule: __device__ globals)
__device__ float  g_q[Bb * Nn * Dd];                 // [b][n][d] f32, pre-scaled by log2e
__device__ float  g_k2[Bb * (Nn / 2) * Dd * 2];      // [b][kp][d][2] f32 key-pair interleaved
__device__ __half g_vh[Bb * (Nn / 2) * Cc * 2];      // [b][kp][c][2] f16 key-pair interleaved

// ---------------- PTX helpers (baseline ISA only) ----------------
__device__ __forceinline__ uint32_t smem_u32(const void* p) {
    uint32_t a;
    asm("{ .reg .u64 t; cvta.to.shared.u64 t, %1; cvt.u32.u64 %0, t; }" : "=r"(a) : "l"(p));
    return a;
}
__device__ __forceinline__ unsigned long long pack2(float a, float b) {
    unsigned long long r;
    asm("mov.b64 %0, {%1, %2};" : "=l"(r) : "f"(a), "f"(b));
    return r;
}
__device__ __forceinline__ void unpack2(unsigned long long v, float& a, float& b) {
    asm("mov.b64 {%0, %1}, %2;" : "=f"(a), "=f"(b) : "l"(v));
}
__device__ __forceinline__ unsigned long long ffma2(unsigned long long a,
                                                    unsigned long long b,
                                                    unsigned long long c) {
    unsigned long long d;
    asm("fma.rn.f32x2 %0, %1, %2, %3;" : "=l"(d) : "l"(a), "l"(b), "l"(c));
    return d;
}
__device__ __forceinline__ unsigned long long fmul2(unsigned long long a,
                                                    unsigned long long b) {
    unsigned long long d;
    asm("mul.rn.f32x2 %0, %1, %2;" : "=l"(d) : "l"(a), "l"(b));
    return d;
}
__device__ __forceinline__ float ex2f(float x) {
    float y;
    asm("ex2.approx.ftz.f32 %0, %1;" : "=f"(y) : "f"(x));
    return y;
}
// d = {lo, hi} as f16x2 (lo in low half)
__device__ __forceinline__ uint32_t cvtf16x2(float lo, float hi) {
    uint32_t r;
    asm("cvt.rn.f16x2.f32 %0, %1, %2;" : "=r"(r) : "f"(hi), "f"(lo));
    return r;
}
__device__ __forceinline__ void lds_v2u64(uint32_t a, unsigned long long& x,
                                          unsigned long long& y) {
    asm volatile("ld.shared.v2.u64 {%0, %1}, [%2];" : "=l"(x), "=l"(y) : "r"(a));
}
__device__ __forceinline__ uint32_t lds32(uint32_t a) {
    uint32_t r;
    asm volatile("ld.shared.b32 %0, [%1];" : "=r"(r) : "r"(a));
    return r;
}
__device__ __forceinline__ void cp16(uint32_t dst, const void* src) {
    asm volatile("cp.async.ca.shared.global [%0], [%1], 16;" :: "r"(dst), "l"(src) : "memory");
}
#define CP_COMMIT() asm volatile("cp.async.commit_group;" ::: "memory")
#define CP_WAIT1()  asm volatile("cp.async.wait_group 1;" ::: "memory")
#define CP_WAIT0()  asm volatile("cp.async.wait_group 0;" ::: "memory")

__device__ __forceinline__ void mma16816(float d[4], uint32_t a0, uint32_t a1,
                                         uint32_t a2, uint32_t a3,
                                         uint32_t b0, uint32_t b1) {
    asm volatile(
        "mma.sync.aligned.m16n8k16.row.col.f32.f16.f16.f32 "
        "{%0,%1,%2,%3}, {%4,%5,%6,%7}, {%8,%9}, {%0,%1,%2,%3};"
        : "+f"(d[0]), "+f"(d[1]), "+f"(d[2]), "+f"(d[3])
        : "r"(a0), "r"(a1), "r"(a2), "r"(a3), "r"(b0), "r"(b1));
}

// ============================================================
// Kernel 1: fused 1x1-conv QKV projection
//   q -> g_q  (f32, scaled by log2e)
//   k -> g_k2 (f32, key-pair interleaved [kp][d][2])
//   v -> g_vh (f16, key-pair interleaved [kp][c][2])
// ============================================================
__global__ void __launch_bounds__(128) qkv_kernel(
    const float* __restrict__ x,
    const float* __restrict__ Wq, const float* __restrict__ bq,
    const float* __restrict__ Wk, const float* __restrict__ bk,
    const float* __restrict__ Wv, const float* __restrict__ bv)
{
    __shared__ float sWq[Dd * Cc];
    __shared__ float sWk[Dd * Cc];
    __shared__ float sWv[Cc * Cc];
    __shared__ float sbq[Dd], sbk[Dd], sbv[Cc];

    const int tid = threadIdx.x;
    const int b = blockIdx.y;
    const int n = blockIdx.x * 128 + tid;

    for (int i = tid; i < Dd * Cc; i += 128) { sWq[i] = Wq[i]; sWk[i] = Wk[i]; }
    for (int i = tid; i < Cc * Cc; i += 128) sWv[i] = Wv[i];
    if (tid < Dd) { sbq[tid] = bq[tid]; sbk[tid] = bk[tid]; }
    if (tid < Cc) sbv[tid] = bv[tid];
    __syncthreads();

    float aq[Dd], ak[Dd], av[Cc];
#pragma unroll
    for (int d = 0; d < Dd; d++) { aq[d] = sbq[d]; ak[d] = sbk[d]; }
#pragma unroll
    for (int c = 0; c < Cc; c++) av[c] = sbv[c];

    const float* xp = x + (size_t)b * Cc * Nn + n;
#pragma unroll 4
    for (int c = 0; c < Cc; c++) {
        const float xc = xp[c * Nn];
#pragma unroll
        for (int d = 0; d < Dd; d++) {
            aq[d] = fmaf(sWq[d * Cc + c], xc, aq[d]);
            ak[d] = fmaf(sWk[d * Cc + c], xc, ak[d]);
        }
#pragma unroll
        for (int e = 0; e < Cc; e++)
            av[e] = fmaf(sWv[e * Cc + c], xc, av[e]);
    }

    float4* qd = (float4*)&g_q[((size_t)b * Nn + n) * Dd];
    qd[0] = make_float4(aq[0] * LOG2E, aq[1] * LOG2E, aq[2] * LOG2E, aq[3] * LOG2E);
    qd[1] = make_float4(aq[4] * LOG2E, aq[5] * LOG2E, aq[6] * LOG2E, aq[7] * LOG2E);

    const size_t kpb = (size_t)b * (Nn / 2) + (n >> 1);
    const int odd = n & 1;
#pragma unroll
    for (int d = 0; d < Dd; d++)
        g_k2[kpb * 16 + d * 2 + odd] = ak[d];
#pragma unroll
    for (int c = 0; c < Cc; c++)
        g_vh[kpb * (Cc * 2) + c * 2 + odd] = __float2half_rn(av[c]);
}

// ============================================================
// Kernel 2: flash attention, P·V via mma.sync (f16 -> f32)
//   256 threads = 8 warps; warp w owns queries w*16..w*16+15.
//   Per 16-key step: logits fp32 (ffma2) -> exp2 -> f16x2 A-frags
//   (register-resident, layout-exact), V B-frags from swizzled smem.
// grid (Nn/NQ = 32, Bb), 256 threads
// ============================================================
__global__ void __launch_bounds__(256, 1) attn_kernel(
    const float* __restrict__ x,
    const float* __restrict__ gamma,
    float* __restrict__ out)
{
    // double buffer: per buf 4KB K + 16KB V; epilogue reuses as 64x132 f32
    __shared__ __align__(16) char smem[40960];
    const uint32_t sb = smem_u32(smem);

    const int tid  = threadIdx.x;
    const int w    = tid >> 5;
    const int lane = tid & 31;
    const int gid  = lane >> 2;   // 0..7
    const int tg   = lane & 3;    // 0..3
    const int b    = blockIdx.y;
    const int row0 = blockIdx.x * NQ;

    // ---- load q for rows (gid) and (gid+8) of this warp's 16-query block ----
    unsigned long long qp0[8], qp1[8];
    {
        const float4* q0p = (const float4*)&g_q[((size_t)b * Nn + row0 + w * 16 + gid) * Dd];
        const float4* q1p = (const float4*)&g_q[((size_t)b * Nn + row0 + w * 16 + gid + 8) * Dd];
        float qa[8], qb[8];
        float4 t0 = q0p[0], t1 = q0p[1], t2 = q1p[0], t3 = q1p[1];
        qa[0] = t0.x; qa[1] = t0.y; qa[2] = t0.z; qa[3] = t0.w;
        qa[4] = t1.x; qa[5] = t1.y; qa[6] = t1.z; qa[7] = t1.w;
        qb[0] = t2.x; qb[1] = t2.y; qb[2] = t2.z; qb[3] = t2.w;
        qb[4] = t3.x; qb[5] = t3.y; qb[6] = t3.z; qb[7] = t3.w;
#pragma unroll
        for (int d = 0; d < 8; d++) {
            qp0[d] = pack2(qa[d], qa[d]);
            qp1[d] = pack2(qb[d], qb[d]);
        }
    }

    // swizzled V-fragment offsets (constant per thread)
    uint32_t swA[8], swB[8];
#pragma unroll
    for (int nt = 0; nt < 8; nt++) {
        swA[nt] = (uint32_t)(((nt * 8 + gid) ^ (tg * 8)) * 4);
        swB[nt] = (uint32_t)(((nt * 8 + gid) ^ (tg * 8 + 32)) * 4);
    }

    float dac[8][4];
#pragma unroll
    for (int nt = 0; nt < 8; nt++)
#pragma unroll
        for (int i = 0; i < 4; i++) dac[nt][i] = 0.f;
    float l0 = 0.f, l1 = 0.f;

    // ---- prefetch helper ----
    auto prefetch = [&](int t, int buf) {
        const uint32_t kdst = sb + (uint32_t)buf * 20480u;
        const uint32_t vdst = kdst + 4096u;
        {
            const int kp = tid >> 2, part = tid & 3;
            const float* src = &g_k2[((size_t)(b * (Nn / 2) + t * 64 + kp)) * 16 + part * 4];
            cp16(kdst + (uint32_t)(kp * 64 + part * 16), src);
        }
#pragma unroll
        for (int j = 0; j < 4; j++) {
            const int id = tid + 256 * j;
            const int kp = id >> 4, part = id & 15;
            const __half* src = &g_vh[((size_t)(b * (Nn / 2) + t * 64 + kp)) * 128 + part * 8];
            const uint32_t csw = (uint32_t)((part * 4) ^ ((kp & 7) * 8));
            cp16(vdst + (uint32_t)(kp * 256) + csw * 4u, src);
        }
    };

    prefetch(0, 0);
    CP_COMMIT();

#pragma unroll 1
    for (int t = 0; t < NT; t++) {
        if (t + 1 < NT) { prefetch(t + 1, (t + 1) & 1); CP_COMMIT(); CP_WAIT1(); }
        else           { CP_WAIT0(); }
        __syncthreads();

        const uint32_t Kb = sb + (uint32_t)(t & 1) * 20480u;
        const uint32_t Vb = Kb + 4096u;

#pragma unroll
        for (int ks = 0; ks < 8; ks++) {
            // K pairs kpA = ks*8+tg, kpB = kpA+4
            const uint32_t kaA = Kb + (uint32_t)((ks * 8 + tg) * 64);
            const uint32_t kaB = kaA + 256u;
            unsigned long long kA[8], kB[8];
            lds_v2u64(kaA,      kA[0], kA[1]);
            lds_v2u64(kaA + 16, kA[2], kA[3]);
            lds_v2u64(kaA + 32, kA[4], kA[5]);
            lds_v2u64(kaA + 48, kA[6], kA[7]);
            lds_v2u64(kaB,      kB[0], kB[1]);
            lds_v2u64(kaB + 16, kB[2], kB[3]);
            lds_v2u64(kaB + 32, kB[4], kB[5]);
            lds_v2u64(kaB + 48, kB[6], kB[7]);

            unsigned long long aA0 = fmul2(qp0[0], kA[0]);
            unsigned long long aA1 = fmul2(qp1[0], kA[0]);
            unsigned long long aB0 = fmul2(qp0[0], kB[0]);
            unsigned long long aB1 = fmul2(qp1[0], kB[0]);
#pragma unroll
            for (int d = 1; d < 8; d++) {
                aA0 = ffma2(qp0[d], kA[d], aA0);
                aA1 = ffma2(qp1[d], kA[d], aA1);
                aB0 = ffma2(qp0[d], kB[d], aB0);
                aB1 = ffma2(qp1[d], kB[d], aB1);
            }
            float sA0l, sA0h, sA1l, sA1h, sB0l, sB0h, sB1l, sB1h;
            unpack2(aA0, sA0l, sA0h);
            unpack2(aA1, sA1l, sA1h);
            unpack2(aB0, sB0l, sB0h);
            unpack2(aB1, sB1l, sB1h);
            const float eA0l = ex2f(sA0l), eA0h = ex2f(sA0h);
            const float eA1l = ex2f(sA1l), eA1h = ex2f(sA1h);
            const float eB0l = ex2f(sB0l), eB0h = ex2f(sB0h);
            const float eB1l = ex2f(sB1l), eB1h = ex2f(sB1h);
            l0 += eA0l + eA0h + eB0l + eB0h;
            l1 += eA1l + eA1h + eB1l + eB1h;
            const uint32_t a0 = cvtf16x2(eA0l, eA0h);
            const uint32_t a1 = cvtf16x2(eA1l, eA1h);
            const uint32_t a2 = cvtf16x2(eB0l, eB0h);
            const uint32_t a3 = cvtf16x2(eB1l, eB1h);

            const uint32_t vA = Vb + (uint32_t)((ks * 8 + tg) * 256);
            const uint32_t vB = vA + 1024u;
#pragma unroll
            for (int nt = 0; nt < 8; nt++) {
                const uint32_t b0 = lds32(vA + swA[nt]);
                const uint32_t b1 = lds32(vB + swB[nt]);
                mma16816(dac[nt], a0, a1, a2, a3, b0, b1);
            }
        }
        __syncthreads();
    }

    // ---- l reduce across the 4 tg lanes sharing each query ----
    l0 += __shfl_xor_sync(0xFFFFFFFFu, l0, 1);
    l0 += __shfl_xor_sync(0xFFFFFFFFu, l0, 2);
    l1 += __shfl_xor_sync(0xFFFFFFFFu, l1, 1);
    l1 += __shfl_xor_sync(0xFFFFFFFFu, l1, 2);
    const float li0 = 1.0f / l0;
    const float li1 = 1.0f / l1;

    // ---- transpose through smem (stride 132 = conflict-free) ----
    float* sD = (float*)smem;
#pragma unroll
    for (int nt = 0; nt < 8; nt++) {
        const int c = nt * 8 + tg * 2;
        const int r = w * 16 + gid;
        sD[c * 132 + r]           = dac[nt][0] * li0;
        sD[(c + 1) * 132 + r]     = dac[nt][1] * li0;
        sD[c * 132 + r + 8]       = dac[nt][2] * li1;
        sD[(c + 1) * 132 + r + 8] = dac[nt][3] * li1;
    }
    __syncthreads();

    // ---- coalesced epilogue: out = gamma * attn + x ----
    const float gm = __ldg(gamma);
#pragma unroll
    for (int k = 0; k < 8; k++) {
        const int flat = tid + 256 * k;
        const int c = flat >> 5, seg = flat & 31;
        const float4 v = *(const float4*)&sD[c * 132 + seg * 4];
        const size_t gidx = ((size_t)(b * Cc + c)) * Nn + row0 + seg * 4;
        const float4 xv = *(const float4*)&x[gidx];
        float4 o;
        o.x = fmaf(gm, v.x, xv.x);
        o.y = fmaf(gm, v.y, xv.y);
        o.z = fmaf(gm, v.z, xv.z);
        o.w = fmaf(gm, v.w, xv.w);
        *(float4*)&out[gidx] = o;
    }
}

// ============================================================
extern "C" void kernel_launch(void* const* d_in, const int* in_sizes, int n_in,
                              void* d_out, int out_size)
{
    const float* x     = (const float*)d_in[0];
    const float* Wq    = (const float*)d_in[1];
    const float* bq    = (const float*)d_in[2];
    const float* Wk    = (const float*)d_in[3];
    const float* bk    = (const float*)d_in[4];
    const float* Wv    = (const float*)d_in[5];
    const float* bv    = (const float*)d_in[6];
    const float* gamma = (const float*)d_in[7];
    float* out = (float*)d_out;

    dim3 g1(Nn / 128, Bb);
    qkv_kernel<<<g1, 128>>>(x, Wq, bq, Wk, bk, Wv, bv);

    dim3 g2(Nn / NQ, Bb);
    attn_kernel<<<g2, 256>>>(x, gamma, out);
}

// round 6
// speedup vs baseline: 6.6826x; 1.8039x over previous
#include <cuda_runtime.h>
#include <cuda_fp16.h>
#include <cstdint>

// Problem constants
#define Bb 4
#define Cc 64
#define Dd 8
#define Nn 4096          // H*W
#define LOG2E 1.4426950408889634f
#define TK 128           // keys per tile
#define NQ 128           // queries per CTA
#define KS 2             // key splits
#define NTS (Nn / TK / KS)   // 16 tiles per CTA

// Scratch (allocation-free rule: __device__ globals)
__device__ float  g_q[Bb * Nn * Dd];                 // [b][n][d] f32, scaled by log2e
__device__ __half g_kh[Bb * Nn * Dd];                // [b][n][d] f16
__device__ __half g_vh[Bb * (Nn / 2) * Cc * 2];      // [b][kp][c][2] f16 key-pair interleaved
__device__ float  g_po[Bb * KS * Cc * Nn];           // partial O (unnormalized)
__device__ float  g_pl[Bb * KS * Nn];                // partial l

// ---------------- PTX helpers (baseline ISA only) ----------------
__device__ __forceinline__ uint32_t smem_u32(const void* p) {
    uint32_t a;
    asm("{ .reg .u64 t; cvta.to.shared.u64 t, %1; cvt.u32.u64 %0, t; }" : "=r"(a) : "l"(p));
    return a;
}
// d = {lo, hi} f16x2 (lo in low half)
__device__ __forceinline__ uint32_t cvtf16x2(float lo, float hi) {
    uint32_t r;
    asm("cvt.rn.f16x2.f32 %0, %1, %2;" : "=r"(r) : "f"(hi), "f"(lo));
    return r;
}
__device__ __forceinline__ uint32_t ex2h2(uint32_t a) {
    uint32_t r;
    asm("ex2.approx.f16x2 %0, %1;" : "=r"(r) : "r"(a));
    return r;
}
__device__ __forceinline__ uint32_t lds32(uint32_t a) {
    uint32_t r;
    asm volatile("ld.shared.b32 %0, [%1];" : "=r"(r) : "r"(a));
    return r;
}
__device__ __forceinline__ void cp16(uint32_t dst, const void* src) {
    asm volatile("cp.async.ca.shared.global [%0], [%1], 16;" :: "r"(dst), "l"(src) : "memory");
}
#define CP_COMMIT() asm volatile("cp.async.commit_group;" ::: "memory")
#define CP_WAIT1()  asm volatile("cp.async.wait_group 1;" ::: "memory")
#define CP_WAIT0()  asm volatile("cp.async.wait_group 0;" ::: "memory")

// S[16q x 8k] = Q[16x8] * K^T, f32 accum from zero
__device__ __forceinline__ void mma_qk8(float s[4], uint32_t a0, uint32_t a1,
                                        uint32_t b0) {
    asm volatile(
        "mma.sync.aligned.m16n8k8.row.col.f32.f16.f16.f32 "
        "{%0,%1,%2,%3}, {%4,%5}, {%6}, {%7,%7,%7,%7};"
        : "=f"(s[0]), "=f"(s[1]), "=f"(s[2]), "=f"(s[3])
        : "r"(a0), "r"(a1), "r"(b0), "f"(0.0f));
}
__device__ __forceinline__ void mma16816(float d[4], uint32_t a0, uint32_t a1,
                                         uint32_t a2, uint32_t a3,
                                         uint32_t b0, uint32_t b1) {
    asm volatile(
        "mma.sync.aligned.m16n8k16.row.col.f32.f16.f16.f32 "
        "{%0,%1,%2,%3}, {%4,%5,%6,%7}, {%8,%9}, {%0,%1,%2,%3};"
        : "+f"(d[0]), "+f"(d[1]), "+f"(d[2]), "+f"(d[3])
        : "r"(a0), "r"(a1), "r"(a2), "r"(a3), "r"(b0), "r"(b1));
}

// ============================================================
// Kernel 1: fused 1x1-conv QKV projection
//   256 threads: 64 pixels x 4 channel-groups.
//   cg0: v[0:16] + q; cg1: v[16:32] + k; cg2: v[32:48]; cg3: v[48:64]
// grid (Nn/64, Bb)
// ============================================================
__global__ void __launch_bounds__(256) qkv_kernel(
    const float* __restrict__ x,
    const float* __restrict__ Wq, const float* __restrict__ bq,
    const float* __restrict__ Wk, const float* __restrict__ bk,
    const float* __restrict__ Wv, const float* __restrict__ bv)
{
    __shared__ float sWv[Cc * Cc];
    __shared__ float sWq[Dd * Cc];
    __shared__ float sWk[Dd * Cc];
    __shared__ float sbv[Cc], sbq[Dd], sbk[Dd];

    const int tid = threadIdx.x;
    const int nl  = tid & 63;
    const int cg  = tid >> 6;
    const int b   = blockIdx.y;
    const int n   = blockIdx.x * 64 + nl;

    for (int i = tid; i < Cc * Cc; i += 256) sWv[i] = Wv[i];
    for (int i = tid; i < Dd * Cc; i += 256) { sWq[i] = Wq[i]; sWk[i] = Wk[i]; }
    if (tid < Cc) sbv[tid] = bv[tid];
    if (tid < Dd) { sbq[tid] = bq[tid]; sbk[tid] = bk[tid]; }
    __syncthreads();

    float av[16];
#pragma unroll
    for (int j = 0; j < 16; j++) av[j] = sbv[cg * 16 + j];
    float aqk[Dd];
#pragma unroll
    for (int d = 0; d < Dd; d++)
        aqk[d] = (cg == 0) ? sbq[d] : sbk[d];

    const float* xp = x + (size_t)b * Cc * Nn + n;
    const float* wv = &sWv[cg * 16 * Cc];
#pragma unroll 4
    for (int c = 0; c < Cc; c++) {
        const float xc = xp[c * Nn];
#pragma unroll
        for (int j = 0; j < 16; j++)
            av[j] = fmaf(wv[j * Cc + c], xc, av[j]);
        if (cg == 0) {
#pragma unroll
            for (int d = 0; d < Dd; d++)
                aqk[d] = fmaf(sWq[d * Cc + c], xc, aqk[d]);
        } else if (cg == 1) {
#pragma unroll
            for (int d = 0; d < Dd; d++)
                aqk[d] = fmaf(sWk[d * Cc + c], xc, aqk[d]);
        }
    }

    // V: pair neighbor pixels (n even/odd) into f16x2, even lanes write
    const int odd = n & 1;
    const size_t kpb = (size_t)b * (Nn / 2) + (n >> 1);
    uint32_t* vdst = (uint32_t*)&g_vh[kpb * (Cc * 2)];
#pragma unroll
    for (int j = 0; j < 16; j++) {
        const float other = __shfl_xor_sync(0xFFFFFFFFu, av[j], 1);
        if (!odd) {
            uint32_t pk = cvtf16x2(av[j], other);
            vdst[cg * 16 + j] = pk;
        }
    }

    if (cg == 0) {
        float4* qd = (float4*)&g_q[((size_t)b * Nn + n) * Dd];
        qd[0] = make_float4(aqk[0] * LOG2E, aqk[1] * LOG2E,
                            aqk[2] * LOG2E, aqk[3] * LOG2E);
        qd[1] = make_float4(aqk[4] * LOG2E, aqk[5] * LOG2E,
                            aqk[6] * LOG2E, aqk[7] * LOG2E);
    } else if (cg == 1) {
        uint32_t kp[4];
#pragma unroll
        for (int i = 0; i < 4; i++)
            kp[i] = cvtf16x2(aqk[2 * i], aqk[2 * i + 1]);
        asm volatile("st.global.v4.b32 [%0], {%1, %2, %3, %4};"
                     :: "l"(&g_kh[((size_t)b * Nn + n) * Dd]),
                        "r"(kp[0]), "r"(kp[1]), "r"(kp[2]), "r"(kp[3]) : "memory");
    }
}

// ============================================================
// Kernel 2: attention, QK^T and P·V both on mma.sync.
//   grid (32, KS, Bb), 256 threads = 8 warps (16 queries each).
//   Writes unnormalized partial O and partial l.
// ============================================================
__global__ void __launch_bounds__(256) attn_kernel()
{
    // 2 bufs x (2KB K + 16KB V); epilogue reuses as 64x132 f32 (33.8KB)
    __shared__ __align__(16) char smem[36864];
    const uint32_t sb = smem_u32(smem);

    const int tid  = threadIdx.x;
    const int w    = tid >> 5;
    const int lane = tid & 31;
    const int gid  = lane >> 2;   // 0..7
    const int tg   = lane & 3;    // 0..3
    const int b    = blockIdx.z;
    const int s    = blockIdx.y;
    const int row0 = blockIdx.x * NQ;
    const int key0 = s * (Nn / KS);

    // ---- Q A-frags for QK mma (constant) ----
    uint32_t qA0, qA1;
    {
        const float* qr = &g_q[((size_t)b * Nn + row0 + w * 16 + gid) * Dd + 2 * tg];
        const float2 qa = *(const float2*)qr;
        const float2 qc = *(const float2*)(qr + 8 * Dd);
        qA0 = cvtf16x2(qa.x, qa.y);
        qA1 = cvtf16x2(qc.x, qc.y);
    }

    // swizzled V-fragment offsets (constant per thread)
    uint32_t swA[8], swB[8];
#pragma unroll
    for (int nt = 0; nt < 8; nt++) {
        swA[nt] = (uint32_t)(((nt * 8 + gid) ^ (tg * 8)) * 4);
        swB[nt] = (uint32_t)(((nt * 8 + gid) ^ (tg * 8 + 32)) * 4);
    }

    float dac[8][4];
#pragma unroll
    for (int nt = 0; nt < 8; nt++)
#pragma unroll
        for (int i = 0; i < 4; i++) dac[nt][i] = 0.f;
    float dl[4] = {0.f, 0.f, 0.f, 0.f};
    const uint32_t ONES = 0x3C003C00u;

    auto prefetch = [&](int t, int buf) {
        const uint32_t kdst = sb + (uint32_t)buf * 18432u;
        const uint32_t vdst = kdst + 2048u;
        if (tid < 128)
            cp16(kdst + (uint32_t)(tid * 16),
                 &g_kh[((size_t)b * Nn + key0 + t * TK + tid) * Dd]);
#pragma unroll
        for (int j = 0; j < 4; j++) {
            const int id = tid + 256 * j;
            const int kp = id >> 4, part = id & 15;
            const __half* src =
                &g_vh[((size_t)(b * (Nn / 2) + (key0 >> 1) + t * 64 + kp)) * 128 + part * 8];
            const uint32_t csw = (uint32_t)((part * 4) ^ ((kp & 7) * 8));
            cp16(vdst + (uint32_t)(kp * 256) + csw * 4u, src);
        }
    };

    prefetch(0, 0);
    CP_COMMIT();

#pragma unroll 1
    for (int t = 0; t < NTS; t++) {
        if (t + 1 < NTS) { prefetch(t + 1, (t + 1) & 1); CP_COMMIT(); CP_WAIT1(); }
        else             { CP_WAIT0(); }
        __syncthreads();

        const uint32_t Kb = sb + (uint32_t)(t & 1) * 18432u;
        const uint32_t Vb = Kb + 2048u;

#pragma unroll
        for (int ks = 0; ks < 8; ks++) {
            // ---- QK^T: two m16n8k8 for 16 keys ----
            const uint32_t kaddr = Kb + (uint32_t)(ks * 256 + gid * 16 + tg * 4);
            const uint32_t kb0 = lds32(kaddr);
            const uint32_t kb1 = lds32(kaddr + 128u);
            float s0[4], s1[4];
            mma_qk8(s0, qA0, qA1, kb0);
            mma_qk8(s1, qA0, qA1, kb1);

            // ---- exp2 in f16x2 -> A-frags ----
            const uint32_t a0 = ex2h2(cvtf16x2(s0[0], s0[1]));
            const uint32_t a1 = ex2h2(cvtf16x2(s0[2], s0[3]));
            const uint32_t a2 = ex2h2(cvtf16x2(s1[0], s1[1]));
            const uint32_t a3 = ex2h2(cvtf16x2(s1[2], s1[3]));

            // ---- P·V + l ----
            const uint32_t vA = Vb + (uint32_t)((ks * 8 + tg) * 256);
            const uint32_t vB = vA + 1024u;
#pragma unroll
            for (int nt = 0; nt < 8; nt++) {
                const uint32_t b0 = lds32(vA + swA[nt]);
                const uint32_t b1 = lds32(vB + swB[nt]);
                mma16816(dac[nt], a0, a1, a2, a3, b0, b1);
            }
            mma16816(dl, a0, a1, a2, a3, ONES, ONES);
        }
        __syncthreads();
    }

    // ---- partial l ----
    if (tg == 0) {
        const size_t lb = ((size_t)(b * KS + s)) * Nn + row0 + w * 16 + gid;
        g_pl[lb]     = dl[0];
        g_pl[lb + 8] = dl[2];
    }

    // ---- transpose unnormalized O through smem (stride 132) ----
    float* sD = (float*)smem;
#pragma unroll
    for (int nt = 0; nt < 8; nt++) {
        const int c = nt * 8 + tg * 2;
        const int r = w * 16 + gid;
        sD[c * 132 + r]           = dac[nt][0];
        sD[(c + 1) * 132 + r]     = dac[nt][1];
        sD[c * 132 + r + 8]       = dac[nt][2];
        sD[(c + 1) * 132 + r + 8] = dac[nt][3];
    }
    __syncthreads();

#pragma unroll
    for (int k = 0; k < 8; k++) {
        const int flat = tid + 256 * k;
        const int c = flat >> 5, seg = flat & 31;
        const float4 v = *(const float4*)&sD[c * 132 + seg * 4];
        *(float4*)&g_po[(((size_t)(b * KS + s) * Cc + c)) * Nn + row0 + seg * 4] = v;
    }
}

// ============================================================
// Kernel 3: merge splits + gamma residual
// ============================================================
__global__ void __launch_bounds__(256) reduce_kernel(
    const float* __restrict__ x,
    const float* __restrict__ gamma,
    float* __restrict__ out)
{
    const int i = blockIdx.x * 256 + threadIdx.x;
    const size_t flat = (size_t)i * 4;
    const int b = (int)(flat / ((size_t)Cc * Nn));
    const int rem = (int)(flat - (size_t)b * Cc * Nn);
    const int c = rem / Nn;
    const int n = rem % Nn;

    const float4 o0 = *(const float4*)&g_po[(((size_t)(b * KS) * Cc + c)) * Nn + n];
    const float4 o1 = *(const float4*)&g_po[(((size_t)(b * KS + 1) * Cc + c)) * Nn + n];
    const float4 l0 = *(const float4*)&g_pl[((size_t)(b * KS)) * Nn + n];
    const float4 l1 = *(const float4*)&g_pl[((size_t)(b * KS + 1)) * Nn + n];
    const float4 xv = *(const float4*)&x[flat];
    const float gm = __ldg(gamma);

    float4 r;
    r.x = fmaf(gm, (o0.x + o1.x) / (l0.x + l1.x), xv.x);
    r.y = fmaf(gm, (o0.y + o1.y) / (l0.y + l1.y), xv.y);
    r.z = fmaf(gm, (o0.z + o1.z) / (l0.z + l1.z), xv.z);
    r.w = fmaf(gm, (o0.w + o1.w) / (l0.w + l1.w), xv.w);
    *(float4*)&out[flat] = r;
}

// ============================================================
extern "C" void kernel_launch(void* const* d_in, const int* in_sizes, int n_in,
                              void* d_out, int out_size)
{
    const float* x     = (const float*)d_in[0];
    const float* Wq    = (const float*)d_in[1];
    const float* bq    = (const float*)d_in[2];
    const float* Wk    = (const float*)d_in[3];
    const float* bk    = (const float*)d_in[4];
    const float* Wv    = (const float*)d_in[5];
    const float* bv    = (const float*)d_in[6];
    const float* gamma = (const float*)d_in[7];
    float* out = (float*)d_out;

    dim3 g1(Nn / 64, Bb);
    qkv_kernel<<<g1, 256>>>(x, Wq, bq, Wk, bk, Wv, bv);

    dim3 g2(Nn / NQ, KS, Bb);
    attn_kernel<<<g2, 256>>>();

    reduce_kernel<<<(Bb * Cc * Nn / 4) / 256, 256>>>(x, gamma, out);
}

// round 7
// speedup vs baseline: 7.8021x; 1.1675x over previous
#include <cuda_runtime.h>
#include <cuda_fp16.h>
#include <cstdint>

// Problem constants
#define Bb 4
#define Cc 64
#define Dd 8
#define Nn 4096          // H*W
#define LOG2E 1.4426950408889634f
#define TK 128           // keys per tile
#define NQ 128           // queries per CTA
#define KS 2             // key splits
#define NTS (Nn / TK / KS)   // 16 tiles per CTA

// Scratch (allocation-free rule: __device__ globals)
__device__ float  g_q[Bb * Nn * Dd];                 // [b][n][d] f32, scaled by log2e
__device__ __half g_kh[Bb * Nn * Dd];                // [b][n][d] f16
__device__ __half g_vh[Bb * (Nn / 2) * Cc * 2];      // [b][kp][c][2] f16 key-pair interleaved
__device__ float  g_po[Bb * KS * Cc * Nn];           // partial O (unnormalized)
__device__ float  g_pl[Bb * KS * Nn];                // partial l

// ---------------- PTX helpers (baseline ISA only) ----------------
__device__ __forceinline__ uint32_t smem_u32(const void* p) {
    uint32_t a;
    asm("{ .reg .u64 t; cvta.to.shared.u64 t, %1; cvt.u32.u64 %0, t; }" : "=r"(a) : "l"(p));
    return a;
}
__device__ __forceinline__ unsigned long long pack2(float a, float b) {
    unsigned long long r;
    asm("mov.b64 %0, {%1, %2};" : "=l"(r) : "f"(a), "f"(b));
    return r;
}
__device__ __forceinline__ void unpack2(unsigned long long v, float& a, float& b) {
    asm("mov.b64 {%0, %1}, %2;" : "=f"(a), "=f"(b) : "l"(v));
}
__device__ __forceinline__ unsigned long long ffma2(unsigned long long a,
                                                    unsigned long long b,
                                                    unsigned long long c) {
    unsigned long long d;
    asm("fma.rn.f32x2 %0, %1, %2, %3;" : "=l"(d) : "l"(a), "l"(b), "l"(c));
    return d;
}
// d = {lo, hi} f16x2 (lo in low half)
__device__ __forceinline__ uint32_t cvtf16x2(float lo, float hi) {
    uint32_t r;
    asm("cvt.rn.f16x2.f32 %0, %1, %2;" : "=r"(r) : "f"(hi), "f"(lo));
    return r;
}
__device__ __forceinline__ uint32_t ex2h2(uint32_t a) {
    uint32_t r;
    asm("ex2.approx.f16x2 %0, %1;" : "=r"(r) : "r"(a));
    return r;
}
__device__ __forceinline__ uint32_t lds32(uint32_t a) {
    uint32_t r;
    asm volatile("ld.shared.b32 %0, [%1];" : "=r"(r) : "r"(a));
    return r;
}
__device__ __forceinline__ void lds_v2u64(uint32_t a, unsigned long long& x,
                                          unsigned long long& y) {
    asm volatile("ld.shared.v2.u64 {%0, %1}, [%2];" : "=l"(x), "=l"(y) : "r"(a));
}
__device__ __forceinline__ void cp16(uint32_t dst, const void* src) {
    asm volatile("cp.async.ca.shared.global [%0], [%1], 16;" :: "r"(dst), "l"(src) : "memory");
}
#define CP_COMMIT() asm volatile("cp.async.commit_group;" ::: "memory")
#define CP_WAIT1()  asm volatile("cp.async.wait_group 1;" ::: "memory")
#define CP_WAIT0()  asm volatile("cp.async.wait_group 0;" ::: "memory")

// S[16q x 8k] = Q[16x8] * K^T, f32 accum from zero
__device__ __forceinline__ void mma_qk8(float s[4], uint32_t a0, uint32_t a1,
                                        uint32_t b0) {
    asm volatile(
        "mma.sync.aligned.m16n8k8.row.col.f32.f16.f16.f32 "
        "{%0,%1,%2,%3}, {%4,%5}, {%6}, {%7,%7,%7,%7};"
        : "=f"(s[0]), "=f"(s[1]), "=f"(s[2]), "=f"(s[3])
        : "r"(a0), "r"(a1), "r"(b0), "f"(0.0f));
}
__device__ __forceinline__ void mma16816(float d[4], uint32_t a0, uint32_t a1,
                                         uint32_t a2, uint32_t a3,
                                         uint32_t b0, uint32_t b1) {
    asm volatile(
        "mma.sync.aligned.m16n8k16.row.col.f32.f16.f16.f32 "
        "{%0,%1,%2,%3}, {%4,%5,%6,%7}, {%8,%9}, {%0,%1,%2,%3};"
        : "+f"(d[0]), "+f"(d[1]), "+f"(d[2]), "+f"(d[3])
        : "r"(a0), "r"(a1), "r"(a2), "r"(a3), "r"(b0), "r"(b1));
}

// ============================================================
// Kernel 1: fused 1x1-conv QKV projection — weights in REGISTERS,
//   x tile through shared memory (broadcast LDS).
//   320 threads = 4 pixel-groups x 80 output channels.
//   Thread (pg, o): output channel o for 16 pixels, ffma2-packed.
//   o in [0,64): V; [64,72): Q (scaled by log2e); [72,80): K.
// grid (Nn/64, Bb)
// ============================================================
__global__ void __launch_bounds__(320) qkv_kernel(
    const float* __restrict__ x,
    const float* __restrict__ Wq, const float* __restrict__ bq,
    const float* __restrict__ Wk, const float* __restrict__ bk,
    const float* __restrict__ Wv, const float* __restrict__ bv)
{
    __shared__ __align__(16) float sx[Cc * 64];   // [c][px] 16 KB
    const uint32_t sb = smem_u32(sx);

    const int tid = threadIdx.x;
    const int pg  = tid / 80;        // 0..3 (16 pixels each)
    const int o   = tid - pg * 80;   // 0..79
    const int b   = blockIdx.y;
    const int n0  = blockIdx.x * 64;

    // ---- stage x tile [64c][64px] via cp.async ----
#pragma unroll
    for (int i = 0; i < 4; i++) {
        const int id = tid + i * 320;
        if (id < 1024) {
            const int c = id >> 4, chunk = id & 15;
            cp16(sb + (uint32_t)(c * 256 + chunk * 16),
                 &x[(size_t)(b * Cc + c) * Nn + n0 + chunk * 4]);
        }
    }
    CP_COMMIT();

    // ---- select weight row + bias ----
    const float* wsrc;
    float bias, scale;
    if (o < 64)      { wsrc = Wv + o * 64;        bias = bv[o];                scale = 1.0f; }
    else if (o < 72) { wsrc = Wq + (o - 64) * 64; bias = bq[o - 64] * LOG2E;   scale = LOG2E; }
    else             { wsrc = Wk + (o - 72) * 64; bias = bk[o - 72];           scale = 1.0f; }

    unsigned long long acc[8];
#pragma unroll
    for (int i = 0; i < 8; i++) acc[i] = pack2(bias, 0.0f);
    // note: bias only in first lane-pair slot; add properly below instead
#pragma unroll
    for (int i = 0; i < 8; i++) acc[i] = pack2(0.0f, 0.0f);

    CP_WAIT0();
    __syncthreads();

    const uint32_t xrow = sb + (uint32_t)(pg * 64);
#pragma unroll 1
    for (int cb = 0; cb < 4; cb++) {
        // 16 weights -> registers
        const float4 w0 = *(const float4*)(wsrc + cb * 16);
        const float4 w1 = *(const float4*)(wsrc + cb * 16 + 4);
        const float4 w2 = *(const float4*)(wsrc + cb * 16 + 8);
        const float4 w3 = *(const float4*)(wsrc + cb * 16 + 12);
        float wf[16];
        wf[0] = w0.x * scale; wf[1] = w0.y * scale; wf[2] = w0.z * scale; wf[3] = w0.w * scale;
        wf[4] = w1.x * scale; wf[5] = w1.y * scale; wf[6] = w1.z * scale; wf[7] = w1.w * scale;
        wf[8] = w2.x * scale; wf[9] = w2.y * scale; wf[10] = w2.z * scale; wf[11] = w2.w * scale;
        wf[12] = w3.x * scale; wf[13] = w3.y * scale; wf[14] = w3.z * scale; wf[15] = w3.w * scale;

#pragma unroll
        for (int cc = 0; cc < 16; cc++) {
            const uint32_t xa = xrow + (uint32_t)((cb * 16 + cc) * 256);
            unsigned long long x0, x1, x2, x3, x4, x5, x6, x7;
            lds_v2u64(xa,      x0, x1);
            lds_v2u64(xa + 16, x2, x3);
            lds_v2u64(xa + 32, x4, x5);
            lds_v2u64(xa + 48, x6, x7);
            const unsigned long long wp = pack2(wf[cc], wf[cc]);
            acc[0] = ffma2(wp, x0, acc[0]);
            acc[1] = ffma2(wp, x1, acc[1]);
            acc[2] = ffma2(wp, x2, acc[2]);
            acc[3] = ffma2(wp, x3, acc[3]);
            acc[4] = ffma2(wp, x4, acc[4]);
            acc[5] = ffma2(wp, x5, acc[5]);
            acc[6] = ffma2(wp, x6, acc[6]);
            acc[7] = ffma2(wp, x7, acc[7]);
        }
    }

    // ---- epilogue: add bias, store per class ----
    if (o < 64) {
        // V: f16x2 pixel-pair interleave -> g_vh[kp][c][2]
        uint32_t* vd = (uint32_t*)g_vh;
        const size_t kp0 = (size_t)b * (Nn / 2) + (n0 >> 1) + pg * 8;
#pragma unroll
        for (int pp = 0; pp < 8; pp++) {
            float lo, hi;
            unpack2(acc[pp], lo, hi);
            vd[(kp0 + pp) * 64 + o] = cvtf16x2(lo + bias, hi + bias);
        }
    } else if (o < 72) {
        const int d = o - 64;
        float* qd = &g_q[((size_t)b * Nn + n0 + pg * 16) * Dd + d];
#pragma unroll
        for (int pp = 0; pp < 8; pp++) {
            float lo, hi;
            unpack2(acc[pp], lo, hi);
            qd[(2 * pp) * Dd]     = lo + bias;
            qd[(2 * pp + 1) * Dd] = hi + bias;
        }
    } else {
        const int d = o - 72;
        __half* kd = &g_kh[((size_t)b * Nn + n0 + pg * 16) * Dd + d];
#pragma unroll
        for (int pp = 0; pp < 8; pp++) {
            float lo, hi;
            unpack2(acc[pp], lo, hi);
            kd[(2 * pp) * Dd]     = __float2half_rn(lo + bias);
            kd[(2 * pp + 1) * Dd] = __float2half_rn(hi + bias);
        }
    }
}

// ============================================================
// Kernel 2: attention, QK^T and P·V both on mma.sync.
//   grid (32, KS, Bb), 256 threads = 8 warps (16 queries each).
//   Writes unnormalized partial O and partial l.
// ============================================================
__global__ void __launch_bounds__(256) attn_kernel()
{
    // 2 bufs x (2KB K + 16KB V); epilogue reuses as 64x132 f32 (33.8KB)
    __shared__ __align__(16) char smem[36864];
    const uint32_t sb = smem_u32(smem);

    const int tid  = threadIdx.x;
    const int w    = tid >> 5;
    const int lane = tid & 31;
    const int gid  = lane >> 2;   // 0..7
    const int tg   = lane & 3;    // 0..3
    const int b    = blockIdx.z;
    const int s    = blockIdx.y;
    const int row0 = blockIdx.x * NQ;
    const int key0 = s * (Nn / KS);

    // ---- Q A-frags for QK mma (constant) ----
    uint32_t qA0, qA1;
    {
        const float* qr = &g_q[((size_t)b * Nn + row0 + w * 16 + gid) * Dd + 2 * tg];
        const float2 qa = *(const float2*)qr;
        const float2 qc = *(const float2*)(qr + 8 * Dd);
        qA0 = cvtf16x2(qa.x, qa.y);
        qA1 = cvtf16x2(qc.x, qc.y);
    }

    // swizzled V-fragment offsets (constant per thread)
    uint32_t swA[8], swB[8];
#pragma unroll
    for (int nt = 0; nt < 8; nt++) {
        swA[nt] = (uint32_t)(((nt * 8 + gid) ^ (tg * 8)) * 4);
        swB[nt] = (uint32_t)(((nt * 8 + gid) ^ (tg * 8 + 32)) * 4);
    }

    float dac[8][4];
#pragma unroll
    for (int nt = 0; nt < 8; nt++)
#pragma unroll
        for (int i = 0; i < 4; i++) dac[nt][i] = 0.f;
    float dl[4] = {0.f, 0.f, 0.f, 0.f};
    const uint32_t ONES = 0x3C003C00u;

    auto prefetch = [&](int t, int buf) {
        const uint32_t kdst = sb + (uint32_t)buf * 18432u;
        const uint32_t vdst = kdst + 2048u;
        if (tid < 128)
            cp16(kdst + (uint32_t)(tid * 16),
                 &g_kh[((size_t)b * Nn + key0 + t * TK + tid) * Dd]);
#pragma unroll
        for (int j = 0; j < 4; j++) {
            const int id = tid + 256 * j;
            const int kp = id >> 4, part = id & 15;
            const __half* src =
                &g_vh[((size_t)(b * (Nn / 2) + (key0 >> 1) + t * 64 + kp)) * 128 + part * 8];
            const uint32_t csw = (uint32_t)((part * 4) ^ ((kp & 7) * 8));
            cp16(vdst + (uint32_t)(kp * 256) + csw * 4u, src);
        }
    };

    prefetch(0, 0);
    CP_COMMIT();

#pragma unroll 1
    for (int t = 0; t < NTS; t++) {
        if (t + 1 < NTS) { prefetch(t + 1, (t + 1) & 1); CP_COMMIT(); CP_WAIT1(); }
        else             { CP_WAIT0(); }
        __syncthreads();

        const uint32_t Kb = sb + (uint32_t)(t & 1) * 18432u;
        const uint32_t Vb = Kb + 2048u;

#pragma unroll
        for (int ks = 0; ks < 8; ks++) {
            // ---- QK^T: two m16n8k8 for 16 keys ----
            const uint32_t kaddr = Kb + (uint32_t)(ks * 256 + gid * 16 + tg * 4);
            const uint32_t kb0 = lds32(kaddr);
            const uint32_t kb1 = lds32(kaddr + 128u);
            float s0[4], s1[4];
            mma_qk8(s0, qA0, qA1, kb0);
            mma_qk8(s1, qA0, qA1, kb1);

            // ---- exp2 in f16x2 -> A-frags ----
            const uint32_t a0 = ex2h2(cvtf16x2(s0[0], s0[1]));
            const uint32_t a1 = ex2h2(cvtf16x2(s0[2], s0[3]));
            const uint32_t a2 = ex2h2(cvtf16x2(s1[0], s1[1]));
            const uint32_t a3 = ex2h2(cvtf16x2(s1[2], s1[3]));

            // ---- P·V + l ----
            const uint32_t vA = Vb + (uint32_t)((ks * 8 + tg) * 256);
            const uint32_t vB = vA + 1024u;
#pragma unroll
            for (int nt = 0; nt < 8; nt++) {
                const uint32_t b0 = lds32(vA + swA[nt]);
                const uint32_t b1 = lds32(vB + swB[nt]);
                mma16816(dac[nt], a0, a1, a2, a3, b0, b1);
            }
            mma16816(dl, a0, a1, a2, a3, ONES, ONES);
        }
        __syncthreads();
    }

    // ---- partial l ----
    if (tg == 0) {
        const size_t lb = ((size_t)(b * KS + s)) * Nn + row0 + w * 16 + gid;
        g_pl[lb]     = dl[0];
        g_pl[lb + 8] = dl[2];
    }

    // ---- transpose unnormalized O through smem (stride 132) ----
    float* sD = (float*)smem;
#pragma unroll
    for (int nt = 0; nt < 8; nt++) {
        const int c = nt * 8 + tg * 2;
        const int r = w * 16 + gid;
        sD[c * 132 + r]           = dac[nt][0];
        sD[(c + 1) * 132 + r]     = dac[nt][1];
        sD[c * 132 + r + 8]       = dac[nt][2];
        sD[(c + 1) * 132 + r + 8] = dac[nt][3];
    }
    __syncthreads();

#pragma unroll
    for (int k = 0; k < 8; k++) {
        const int flat = tid + 256 * k;
        const int c = flat >> 5, seg = flat & 31;
        const float4 v = *(const float4*)&sD[c * 132 + seg * 4];
        *(float4*)&g_po[(((size_t)(b * KS + s) * Cc + c)) * Nn + row0 + seg * 4] = v;
    }
}

// ============================================================
// Kernel 3: merge splits + gamma residual
// ============================================================
__global__ void __launch_bounds__(256) reduce_kernel(
    const float* __restrict__ x,
    const float* __restrict__ gamma,
    float* __restrict__ out)
{
    const int i = blockIdx.x * 256 + threadIdx.x;
    const size_t flat = (size_t)i * 4;
    const int b = (int)(flat / ((size_t)Cc * Nn));
    const int rem = (int)(flat - (size_t)b * Cc * Nn);
    const int c = rem / Nn;
    const int n = rem % Nn;

    const float4 o0 = *(const float4*)&g_po[(((size_t)(b * KS) * Cc + c)) * Nn + n];
    const float4 o1 = *(const float4*)&g_po[(((size_t)(b * KS + 1) * Cc + c)) * Nn + n];
    const float4 l0 = *(const float4*)&g_pl[((size_t)(b * KS)) * Nn + n];
    const float4 l1 = *(const float4*)&g_pl[((size_t)(b * KS + 1)) * Nn + n];
    const float4 xv = *(const float4*)&x[flat];
    const float gm = __ldg(gamma);

    float4 r;
    r.x = fmaf(gm, (o0.x + o1.x) / (l0.x + l1.x), xv.x);
    r.y = fmaf(gm, (o0.y + o1.y) / (l0.y + l1.y), xv.y);
    r.z = fmaf(gm, (o0.z + o1.z) / (l0.z + l1.z), xv.z);
    r.w = fmaf(gm, (o0.w + o1.w) / (l0.w + l1.w), xv.w);
    *(float4*)&out[flat] = r;
}

// ============================================================
extern "C" void kernel_launch(void* const* d_in, const int* in_sizes, int n_in,
                              void* d_out, int out_size)
{
    const float* x     = (const float*)d_in[0];
    const float* Wq    = (const float*)d_in[1];
    const float* bq    = (const float*)d_in[2];
    const float* Wk    = (const float*)d_in[3];
    const float* bk    = (const float*)d_in[4];
    const float* Wv    = (const float*)d_in[5];
    const float* bv    = (const float*)d_in[6];
    const float* gamma = (const float*)d_in[7];
    float* out = (float*)d_out;

    dim3 g1(Nn / 64, Bb);
    qkv_kernel<<<g1, 320>>>(x, Wq, bq, Wk, bk, Wv, bv);

    dim3 g2(Nn / NQ, KS, Bb);
    attn_kernel<<<g2, 256>>>();

    reduce_kernel<<<(Bb * Cc * Nn / 4) / 256, 256>>>(x, gamma, out);
}

// round 8
// speedup vs baseline: 8.0995x; 1.0381x over previous
#include <cuda_runtime.h>
#include <cuda_fp16.h>
#include <cstdint>

// Problem constants
#define Bb 4
#define Cc 64
#define Dd 8
#define Nn 4096          // H*W
#define LOG2E 1.4426950408889634f
#define TK 128           // keys per tile
#define NQ 128           // queries per CTA
#define KS 2             // key splits
#define NTS (Nn / TK / KS)   // 16 tiles per CTA

// Scratch (allocation-free rule: __device__ globals)
__device__ float  g_q[Bb * Nn * Dd];                 // [b][n][d] f32, scaled by log2e
__device__ __half g_kh[Bb * Nn * Dd];                // [b][n][d] f16
__device__ __half g_vh[Bb * Nn * Cc];                // [b][n][c] f16 key-major
__device__ float  g_po[Bb * KS * Cc * Nn];           // partial O (unnormalized)
__device__ float  g_pl[Bb * KS * Nn];                // partial l

// ---------------- PTX helpers (baseline ISA only) ----------------
__device__ __forceinline__ uint32_t smem_u32(const void* p) {
    uint32_t a;
    asm("{ .reg .u64 t; cvta.to.shared.u64 t, %1; cvt.u32.u64 %0, t; }" : "=r"(a) : "l"(p));
    return a;
}
__device__ __forceinline__ unsigned long long pack2(float a, float b) {
    unsigned long long r;
    asm("mov.b64 %0, {%1, %2};" : "=l"(r) : "f"(a), "f"(b));
    return r;
}
__device__ __forceinline__ void unpack2(unsigned long long v, float& a, float& b) {
    asm("mov.b64 {%0, %1}, %2;" : "=f"(a), "=f"(b) : "l"(v));
}
__device__ __forceinline__ unsigned long long ffma2(unsigned long long a,
                                                    unsigned long long b,
                                                    unsigned long long c) {
    unsigned long long d;
    asm("fma.rn.f32x2 %0, %1, %2, %3;" : "=l"(d) : "l"(a), "l"(b), "l"(c));
    return d;
}
// d = {lo, hi} f16x2 (lo in low half)
__device__ __forceinline__ uint32_t cvtf16x2(float lo, float hi) {
    uint32_t r;
    asm("cvt.rn.f16x2.f32 %0, %1, %2;" : "=r"(r) : "f"(hi), "f"(lo));
    return r;
}
__device__ __forceinline__ uint32_t ex2h2(uint32_t a) {
    uint32_t r;
    asm("ex2.approx.f16x2 %0, %1;" : "=r"(r) : "r"(a));
    return r;
}
__device__ __forceinline__ void lds_v2u64(uint32_t a, unsigned long long& x,
                                          unsigned long long& y) {
    asm volatile("ld.shared.v2.u64 {%0, %1}, [%2];" : "=l"(x), "=l"(y) : "r"(a));
}
__device__ __forceinline__ void ldsm2(uint32_t& r0, uint32_t& r1, uint32_t a) {
    asm volatile("ldmatrix.sync.aligned.m8n8.x2.shared.b16 {%0, %1}, [%2];"
                 : "=r"(r0), "=r"(r1) : "r"(a));
}
__device__ __forceinline__ void ldsm4t(uint32_t& r0, uint32_t& r1, uint32_t& r2,
                                       uint32_t& r3, uint32_t a) {
    asm volatile("ldmatrix.sync.aligned.m8n8.x4.trans.shared.b16 {%0, %1, %2, %3}, [%4];"
                 : "=r"(r0), "=r"(r1), "=r"(r2), "=r"(r3) : "r"(a));
}
__device__ __forceinline__ void cp16(uint32_t dst, const void* src) {
    asm volatile("cp.async.ca.shared.global [%0], [%1], 16;" :: "r"(dst), "l"(src) : "memory");
}
#define CP_COMMIT() asm volatile("cp.async.commit_group;" ::: "memory")
#define CP_WAIT1()  asm volatile("cp.async.wait_group 1;" ::: "memory")
#define CP_WAIT0()  asm volatile("cp.async.wait_group 0;" ::: "memory")

// S[16q x 8k] = Q[16x8] * K^T, f32 accum from zero
__device__ __forceinline__ void mma_qk8(float s[4], uint32_t a0, uint32_t a1,
                                        uint32_t b0) {
    asm volatile(
        "mma.sync.aligned.m16n8k8.row.col.f32.f16.f16.f32 "
        "{%0,%1,%2,%3}, {%4,%5}, {%6}, {%7,%7,%7,%7};"
        : "=f"(s[0]), "=f"(s[1]), "=f"(s[2]), "=f"(s[3])
        : "r"(a0), "r"(a1), "r"(b0), "f"(0.0f));
}
__device__ __forceinline__ void mma16816(float d[4], uint32_t a0, uint32_t a1,
                                         uint32_t a2, uint32_t a3,
                                         uint32_t b0, uint32_t b1) {
    asm volatile(
        "mma.sync.aligned.m16n8k16.row.col.f32.f16.f16.f32 "
        "{%0,%1,%2,%3}, {%4,%5,%6,%7}, {%8,%9}, {%0,%1,%2,%3};"
        : "+f"(d[0]), "+f"(d[1]), "+f"(d[2]), "+f"(d[3])
        : "r"(a0), "r"(a1), "r"(a2), "r"(a3), "r"(b0), "r"(b1));
}

// ============================================================
// Kernel 1: fused 1x1-conv QKV projection — weights in registers
//   (double-buffered LDG), x tile through shared (broadcast LDS).
//   320 threads = 4 pixel-groups x 80 output channels.
//   o in [0,64): V; [64,72): Q (scaled by log2e); [72,80): K.
// grid (Nn/64, Bb)
// ============================================================
__global__ void __launch_bounds__(320) qkv_kernel(
    const float* __restrict__ x,
    const float* __restrict__ Wq, const float* __restrict__ bq,
    const float* __restrict__ Wk, const float* __restrict__ bk,
    const float* __restrict__ Wv, const float* __restrict__ bv)
{
    __shared__ __align__(16) float sx[Cc * 64];   // [c][px] 16 KB
    const uint32_t sb = smem_u32(sx);

    const int tid = threadIdx.x;
    const int pg  = tid / 80;        // 0..3 (16 pixels each)
    const int o   = tid - pg * 80;   // 0..79
    const int b   = blockIdx.y;
    const int n0  = blockIdx.x * 64;

    // ---- stage x tile [64c][64px] via cp.async ----
#pragma unroll
    for (int i = 0; i < 4; i++) {
        const int id = tid + i * 320;
        if (id < 1024) {
            const int c = id >> 4, chunk = id & 15;
            cp16(sb + (uint32_t)(c * 256 + chunk * 16),
                 &x[(size_t)(b * Cc + c) * Nn + n0 + chunk * 4]);
        }
    }
    CP_COMMIT();

    // ---- select weight row + bias; prefetch first weight block ----
    const float* wsrc;
    float bias, scale;
    if (o < 64)      { wsrc = Wv + o * 64;        bias = bv[o];              scale = 1.0f; }
    else if (o < 72) { wsrc = Wq + (o - 64) * 64; bias = bq[o - 64] * LOG2E; scale = LOG2E; }
    else             { wsrc = Wk + (o - 72) * 64; bias = bk[o - 72];         scale = 1.0f; }
    const float4* wp4 = (const float4*)wsrc;

    float4 nw0 = wp4[0], nw1 = wp4[1], nw2 = wp4[2], nw3 = wp4[3];

    unsigned long long acc[8];
#pragma unroll
    for (int i = 0; i < 8; i++) acc[i] = pack2(0.0f, 0.0f);

    CP_WAIT0();
    __syncthreads();

    const uint32_t xrow = sb + (uint32_t)(pg * 64);
#pragma unroll
    for (int cb = 0; cb < 4; cb++) {
        float wf[16];
        wf[0] = nw0.x * scale; wf[1] = nw0.y * scale; wf[2] = nw0.z * scale; wf[3] = nw0.w * scale;
        wf[4] = nw1.x * scale; wf[5] = nw1.y * scale; wf[6] = nw1.z * scale; wf[7] = nw1.w * scale;
        wf[8] = nw2.x * scale; wf[9] = nw2.y * scale; wf[10] = nw2.z * scale; wf[11] = nw2.w * scale;
        wf[12] = nw3.x * scale; wf[13] = nw3.y * scale; wf[14] = nw3.z * scale; wf[15] = nw3.w * scale;
        if (cb < 3) {
            nw0 = wp4[(cb + 1) * 4 + 0];
            nw1 = wp4[(cb + 1) * 4 + 1];
            nw2 = wp4[(cb + 1) * 4 + 2];
            nw3 = wp4[(cb + 1) * 4 + 3];
        }

#pragma unroll
        for (int cc = 0; cc < 16; cc++) {
            const uint32_t xa = xrow + (uint32_t)((cb * 16 + cc) * 256);
            unsigned long long x0, x1, x2, x3, x4, x5, x6, x7;
            lds_v2u64(xa,      x0, x1);
            lds_v2u64(xa + 16, x2, x3);
            lds_v2u64(xa + 32, x4, x5);
            lds_v2u64(xa + 48, x6, x7);
            const unsigned long long wp = pack2(wf[cc], wf[cc]);
            acc[0] = ffma2(wp, x0, acc[0]);
            acc[1] = ffma2(wp, x1, acc[1]);
            acc[2] = ffma2(wp, x2, acc[2]);
            acc[3] = ffma2(wp, x3, acc[3]);
            acc[4] = ffma2(wp, x4, acc[4]);
            acc[5] = ffma2(wp, x5, acc[5]);
            acc[6] = ffma2(wp, x6, acc[6]);
            acc[7] = ffma2(wp, x7, acc[7]);
        }
    }

    // ---- epilogue: add bias, store per class ----
    if (o < 64) {
        // V: plain key-major [b][n][c] f16 (coalesced across warp: c = o)
        __half* vd = &g_vh[((size_t)b * Nn + n0 + pg * 16) * Cc + o];
#pragma unroll
        for (int pp = 0; pp < 8; pp++) {
            float lo, hi;
            unpack2(acc[pp], lo, hi);
            vd[(2 * pp) * Cc]     = __float2half_rn(lo + bias);
            vd[(2 * pp + 1) * Cc] = __float2half_rn(hi + bias);
        }
    } else if (o < 72) {
        const int d = o - 64;
        float* qd = &g_q[((size_t)b * Nn + n0 + pg * 16) * Dd + d];
#pragma unroll
        for (int pp = 0; pp < 8; pp++) {
            float lo, hi;
            unpack2(acc[pp], lo, hi);
            qd[(2 * pp) * Dd]     = lo + bias;
            qd[(2 * pp + 1) * Dd] = hi + bias;
        }
    } else {
        const int d = o - 72;
        __half* kd = &g_kh[((size_t)b * Nn + n0 + pg * 16) * Dd + d];
#pragma unroll
        for (int pp = 0; pp < 8; pp++) {
            float lo, hi;
            unpack2(acc[pp], lo, hi);
            kd[(2 * pp) * Dd]     = __float2half_rn(lo + bias);
            kd[(2 * pp + 1) * Dd] = __float2half_rn(hi + bias);
        }
    }
}

// ============================================================
// Kernel 2: attention, QK^T and P·V on mma.sync; fragments via
//   ldmatrix (K: x2, V: x4.trans from key-major swizzled tiles).
//   grid (32, KS, Bb), 256 threads = 8 warps (16 queries each).
//   Writes unnormalized partial O and partial l.
// ============================================================
__global__ void __launch_bounds__(256) attn_kernel()
{
    // 2 bufs x (2KB K + 16KB V); epilogue reuses as 64x132 f32 (33.8KB)
    __shared__ __align__(16) char smem[36864];
    const uint32_t sb = smem_u32(smem);

    const int tid  = threadIdx.x;
    const int w    = tid >> 5;
    const int lane = tid & 31;
    const int gid  = lane >> 2;   // 0..7
    const int tg   = lane & 3;    // 0..3
    const int b    = blockIdx.z;
    const int s    = blockIdx.y;
    const int row0 = blockIdx.x * NQ;
    const int key0 = s * (Nn / KS);

    // ---- Q A-frags for QK mma (constant) ----
    uint32_t qA0, qA1;
    {
        const float* qr = &g_q[((size_t)b * Nn + row0 + w * 16 + gid) * Dd + 2 * tg];
        const float2 qa = *(const float2*)qr;
        const float2 qc = *(const float2*)(qr + 8 * Dd);
        qA0 = cvtf16x2(qa.x, qa.y);
        qA1 = cvtf16x2(qc.x, qc.y);
    }

    // ---- loop-constant ldmatrix lane offsets ----
    // V tile: rows [key][128B], chunk j swizzled by key&7.
    const int koffV = ((lane >> 3) & 1) * 8 + (lane & 7);   // key offset within 16
    const int jhalf = lane >> 4;                            // chunk half (0/1)
    uint32_t vmoff[4];
#pragma unroll
    for (int g = 0; g < 4; g++)
        vmoff[g] = (uint32_t)(koffV * 128 + (((g * 2 + jhalf) ^ (koffV & 7)) * 16));
    // K tile: rows [key][16B], lanes 0-15 supply 16 key-row addresses.
    const uint32_t kmoff = (uint32_t)((lane & 15) * 16);

    float dac[8][4];
#pragma unroll
    for (int nt = 0; nt < 8; nt++)
#pragma unroll
        for (int i = 0; i < 4; i++) dac[nt][i] = 0.f;
    float dl[4] = {0.f, 0.f, 0.f, 0.f};
    const uint32_t ONES = 0x3C003C00u;

    auto prefetch = [&](int t, int buf) {
        const uint32_t kdst = sb + (uint32_t)buf * 18432u;
        const uint32_t vdst = kdst + 2048u;
        if (tid < 128)
            cp16(kdst + (uint32_t)(tid * 16),
                 &g_kh[((size_t)b * Nn + key0 + t * TK + tid) * Dd]);
#pragma unroll
        for (int j = 0; j < 4; j++) {
            const int id = tid + 256 * j;
            const int key = id >> 3, ch = id & 7;
            cp16(vdst + (uint32_t)(key * 128 + ((ch ^ (key & 7)) * 16)),
                 &g_vh[((size_t)(b * Nn + key0 + t * TK + key)) * Cc + ch * 8]);
        }
    };

    prefetch(0, 0);
    CP_COMMIT();

#pragma unroll 1
    for (int t = 0; t < NTS; t++) {
        if (t + 1 < NTS) { prefetch(t + 1, (t + 1) & 1); CP_COMMIT(); CP_WAIT1(); }
        else             { CP_WAIT0(); }
        __syncthreads();

        const uint32_t Kb = sb + (uint32_t)(t & 1) * 18432u;
        const uint32_t Vb = Kb + 2048u;

#pragma unroll
        for (int ks = 0; ks < 8; ks++) {
            // ---- QK^T: one ldmatrix.x2 + two m16n8k8 for 16 keys ----
            uint32_t kb0, kb1;
            ldsm2(kb0, kb1, Kb + (uint32_t)(ks * 256) + kmoff);
            float s0[4], s1[4];
            mma_qk8(s0, qA0, qA1, kb0);
            mma_qk8(s1, qA0, qA1, kb1);

            // ---- exp2 in f16x2 -> A-frags ----
            const uint32_t a0 = ex2h2(cvtf16x2(s0[0], s0[1]));
            const uint32_t a1 = ex2h2(cvtf16x2(s0[2], s0[3]));
            const uint32_t a2 = ex2h2(cvtf16x2(s1[0], s1[1]));
            const uint32_t a3 = ex2h2(cvtf16x2(s1[2], s1[3]));

            // ---- P·V: 4x ldmatrix.x4.trans covers all 64 channels ----
            const uint32_t vstep = Vb + (uint32_t)(ks * 2048);
#pragma unroll
            for (int g = 0; g < 4; g++) {
                uint32_t r0, r1, r2, r3;
                ldsm4t(r0, r1, r2, r3, vstep + vmoff[g]);
                mma16816(dac[2 * g],     a0, a1, a2, a3, r0, r1);
                mma16816(dac[2 * g + 1], a0, a1, a2, a3, r2, r3);
            }
            mma16816(dl, a0, a1, a2, a3, ONES, ONES);
        }
        __syncthreads();
    }

    // ---- partial l ----
    if (tg == 0) {
        const size_t lb = ((size_t)(b * KS + s)) * Nn + row0 + w * 16 + gid;
        g_pl[lb]     = dl[0];
        g_pl[lb + 8] = dl[2];
    }

    // ---- transpose unnormalized O through smem (stride 132) ----
    float* sD = (float*)smem;
#pragma unroll
    for (int nt = 0; nt < 8; nt++) {
        const int c = nt * 8 + tg * 2;
        const int r = w * 16 + gid;
        sD[c * 132 + r]           = dac[nt][0];
        sD[(c + 1) * 132 + r]     = dac[nt][1];
        sD[c * 132 + r + 8]       = dac[nt][2];
        sD[(c + 1) * 132 + r + 8] = dac[nt][3];
    }
    __syncthreads();

#pragma unroll
    for (int k = 0; k < 8; k++) {
        const int flat = tid + 256 * k;
        const int c = flat >> 5, seg = flat & 31;
        const float4 v = *(const float4*)&sD[c * 132 + seg * 4];
        *(float4*)&g_po[(((size_t)(b * KS + s) * Cc + c)) * Nn + row0 + seg * 4] = v;
    }
}

// ============================================================
// Kernel 3: merge splits + gamma residual
// ============================================================
__global__ void __launch_bounds__(256) reduce_kernel(
    const float* __restrict__ x,
    const float* __restrict__ gamma,
    float* __restrict__ out)
{
    const int i = blockIdx.x * 256 + threadIdx.x;
    const size_t flat = (size_t)i * 4;
    const int b = (int)(flat / ((size_t)Cc * Nn));
    const int rem = (int)(flat - (size_t)b * Cc * Nn);
    const int c = rem / Nn;
    const int n = rem % Nn;

    const float4 o0 = *(const float4*)&g_po[(((size_t)(b * KS) * Cc + c)) * Nn + n];
    const float4 o1 = *(const float4*)&g_po[(((size_t)(b * KS + 1) * Cc + c)) * Nn + n];
    const float4 l0 = *(const float4*)&g_pl[((size_t)(b * KS)) * Nn + n];
    const float4 l1 = *(const float4*)&g_pl[((size_t)(b * KS + 1)) * Nn + n];
    const float4 xv = *(const float4*)&x[flat];
    const float gm = __ldg(gamma);

    float4 r;
    r.x = fmaf(gm, (o0.x + o1.x) / (l0.x + l1.x), xv.x);
    r.y = fmaf(gm, (o0.y + o1.y) / (l0.y + l1.y), xv.y);
    r.z = fmaf(gm, (o0.z + o1.z) / (l0.z + l1.z), xv.z);
    r.w = fmaf(gm, (o0.w + o1.w) / (l0.w + l1.w), xv.w);
    *(float4*)&out[flat] = r;
}

// ============================================================
extern "C" void kernel_launch(void* const* d_in, const int* in_sizes, int n_in,
                              void* d_out, int out_size)
{
    const float* x     = (const float*)d_in[0];
    const float* Wq    = (const float*)d_in[1];
    const float* bq    = (const float*)d_in[2];
    const float* Wk    = (const float*)d_in[3];
    const float* bk    = (const float*)d_in[4];
    const float* Wv    = (const float*)d_in[5];
    const float* bv    = (const float*)d_in[6];
    const float* gamma = (const float*)d_in[7];
    float* out = (float*)d_out;

    dim3 g1(Nn / 64, Bb);
    qkv_kernel<<<g1, 320>>>(x, Wq, bq, Wk, bk, Wv, bv);

    dim3 g2(Nn / NQ, KS, Bb);
    attn_kernel<<<g2, 256>>>();

    reduce_kernel<<<(Bb * Cc * Nn / 4) / 256, 256>>>(x, gamma, out);
}